// round 1
// baseline (speedup 1.0000x reference)
#include <cuda_runtime.h>
#include <cstdint>
#include <cstddef>

// ---------------------------------------------------------------------------
// Static problem geometry (LENGTHS are compile-time constants in the reference)
// ---------------------------------------------------------------------------
#define NGRAPH   16
#define NNODES   4033          // sum(LENGTHS)
#define RREL     4
#define NHEAD    8
#define HDIM     64
#define FIN      256
#define RN       16132         // RREL * NNODES
#define NWIN     132           // kept (non-extra) windows total
#define PROJ     1024          // 512 (Q) + 512 (K) columns

// padded start position of each graph in the L=4736 frame
__constant__ int c_STARTS[NGRAPH] = {0,288,576,896,1184,1472,1792,2080,2400,2688,2976,3264,3552,3840,4160,4448};
// cumulative real-node counts (node index base per graph)
__constant__ int c_CUML[NGRAPH]   = {0,251,498,761,1016,1256,1514,1763,2023,2275,2520,2776,3026,3274,3535,3779};
// real lengths
__constant__ int c_LEN[NGRAPH]    = {251,247,263,255,240,258,249,260,252,245,256,250,248,261,244,254};
// cumulative kept-window counts (kept windows per graph = roundup(len,32)/32)
__constant__ int c_CUMNW[NGRAPH+1]= {0,8,16,25,33,41,50,58,67,75,83,91,99,107,116,124,132};

// scratch: fused Q|K projections, row m = rr*NNODES + node, cols [0,512)=Q, [512,1024)=K
__device__ float g_QK[(size_t)RN * PROJ];   // 66 MB

// ---------------------------------------------------------------------------
// GEMM: C[RN,1024] = A[RN,256] * [Wq;Wk]^T + [bq;bk]
// 128x128 block tile, 8-deep k tiles, 256 threads, 8x8 per-thread microtile.
// ---------------------------------------------------------------------------
__global__ __launch_bounds__(256) void gemm_kernel(
    const float* __restrict__ A,
    const float* __restrict__ Wq, const float* __restrict__ bq,
    const float* __restrict__ Wk, const float* __restrict__ bk)
{
    __shared__ float As[8][132];
    __shared__ float Bs[8][132];

    const int bn  = blockIdx.x;          // 0..7 (column tile)
    const int bm  = blockIdx.y;          // 0..126 (row tile)
    const int m0  = bm * 128;
    const int n0g = bn * 128;            // global col base in [0,1024)

    const float* B;  const float* bias;  int n0;
    if (n0g < 512) { B = Wq; bias = bq; n0 = n0g; }
    else           { B = Wk; bias = bk; n0 = n0g - 512; }

    const int tid = threadIdx.x;
    const int tx  = tid & 15;
    const int ty  = tid >> 4;

    float acc[8][8];
#pragma unroll
    for (int i = 0; i < 8; i++)
#pragma unroll
        for (int j = 0; j < 8; j++) acc[i][j] = 0.f;

    const int lrow = tid >> 1;           // 0..127
    const int lcf  = (tid & 1) * 4;      // 0 or 4

#pragma unroll 1
    for (int k0 = 0; k0 < FIN; k0 += 8) {
        // stage global loads in registers
        float4 av = make_float4(0.f, 0.f, 0.f, 0.f);
        const int gm = m0 + lrow;
        if (gm < RN) av = *reinterpret_cast<const float4*>(A + (size_t)gm * FIN + k0 + lcf);
        float4 bv = *reinterpret_cast<const float4*>(B + (size_t)(n0 + lrow) * FIN + k0 + lcf);

        __syncthreads();                 // previous tile fully consumed
        As[lcf + 0][lrow] = av.x; As[lcf + 1][lrow] = av.y;
        As[lcf + 2][lrow] = av.z; As[lcf + 3][lrow] = av.w;
        Bs[lcf + 0][lrow] = bv.x; Bs[lcf + 1][lrow] = bv.y;
        Bs[lcf + 2][lrow] = bv.z; Bs[lcf + 3][lrow] = bv.w;
        __syncthreads();

#pragma unroll
        for (int kk = 0; kk < 8; kk++) {
            float a[8], b[8];
            *reinterpret_cast<float4*>(&a[0]) = *reinterpret_cast<float4*>(&As[kk][ty * 4]);
            *reinterpret_cast<float4*>(&a[4]) = *reinterpret_cast<float4*>(&As[kk][64 + ty * 4]);
            *reinterpret_cast<float4*>(&b[0]) = *reinterpret_cast<float4*>(&Bs[kk][tx * 4]);
            *reinterpret_cast<float4*>(&b[4]) = *reinterpret_cast<float4*>(&Bs[kk][64 + tx * 4]);
#pragma unroll
            for (int i = 0; i < 8; i++)
#pragma unroll
                for (int j = 0; j < 8; j++)
                    acc[i][j] += a[i] * b[j];
        }
    }

    // epilogue: add bias, vectorized stores
#pragma unroll
    for (int ih = 0; ih < 2; ih++) {
#pragma unroll
        for (int i = 0; i < 4; i++) {
            const int m = m0 + ih * 64 + ty * 4 + i;
            if (m >= RN) continue;
#pragma unroll
            for (int jh = 0; jh < 2; jh++) {
                const int c = jh * 64 + tx * 4;
                float4 v;
                v.x = acc[ih * 4 + i][jh * 4 + 0] + bias[n0 + c + 0];
                v.y = acc[ih * 4 + i][jh * 4 + 1] + bias[n0 + c + 1];
                v.z = acc[ih * 4 + i][jh * 4 + 2] + bias[n0 + c + 2];
                v.w = acc[ih * 4 + i][jh * 4 + 3] + bias[n0 + c + 3];
                *reinterpret_cast<float4*>(&g_QK[(size_t)m * PROJ + n0g + c]) = v;
            }
        }
    }
}

// ---------------------------------------------------------------------------
// Attention: block = (kept window wi, relation rr). 32 queries x 96 keys,
// softmax per head, mean over 8 heads, scatter into banded dense output.
// Warp w owns query rows 4w..4w+3; lane l owns keys {l, 32+l, 64+l}.
// ---------------------------------------------------------------------------
__global__ __launch_bounds__(256) void attn_kernel(float* __restrict__ out)
{
    __shared__ float Qs[32][64];     // [query slot][d]
    __shared__ float Kt[64][97];     // transposed keys, padded stride (conflict-free)
    __shared__ int   qn[32];
    __shared__ int   kn[96];
    __shared__ int   sh_g;

    const int wi  = blockIdx.x;      // kept window index 0..131
    const int rr  = blockIdx.y;      // relation 0..3
    const int tid = threadIdx.x;

    if (tid == 0) {
        int g = 0;
        while (g + 1 < NGRAPH && c_CUMNW[g + 1] <= wi) g++;
        sh_g = g;
    }
    __syncthreads();
    const int g     = sh_g;
    const int pbase = c_STARTS[g] + (wi - c_CUMNW[g]) * 32;

    if (tid < 32) {
        const int k = pbase + tid - c_STARTS[g];
        qn[tid] = (k < c_LEN[g]) ? c_CUML[g] + k : -1;
    } else if (tid < 128) {
        const int c = tid - 32;
        const int k = pbase - 32 + c - c_STARTS[g];
        kn[c] = (k >= 0 && k < c_LEN[g]) ? c_CUML[g] + k : -1;
    }
    __syncthreads();

    const int warp = tid >> 5;
    const int lane = tid & 31;

    float acc[4][3];
#pragma unroll
    for (int i = 0; i < 4; i++)
#pragma unroll
        for (int j = 0; j < 3; j++) acc[i][j] = 0.f;

    const float* Qbase = g_QK + (size_t)rr * NNODES * PROJ;

    const int kidx0 = lane, kidx1 = 32 + lane, kidx2 = 64 + lane;
    const bool v0 = kn[kidx0] >= 0, v1 = kn[kidx1] >= 0, v2 = kn[kidx2] >= 0;

    for (int h = 0; h < NHEAD; h++) {
        // cooperative loads (coalesced on d)
        for (int i = tid; i < 32 * 64; i += 256) {
            const int s = i >> 6, d = i & 63;
            const int node = qn[s];
            Qs[s][d] = (node >= 0) ? Qbase[(size_t)node * PROJ + h * 64 + d] : 0.f;
        }
        for (int i = tid; i < 96 * 64; i += 256) {
            const int c = i >> 6, d = i & 63;
            const int node = kn[c];
            Kt[d][c] = (node >= 0) ? Qbase[(size_t)node * PROJ + 512 + h * 64 + d] : 0.f;
        }
        __syncthreads();

        float lg[4][3];
#pragma unroll
        for (int i = 0; i < 4; i++)
#pragma unroll
            for (int j = 0; j < 3; j++) lg[i][j] = 0.f;

#pragma unroll 4
        for (int d = 0; d < 64; d++) {
            const float k0 = Kt[d][kidx0];
            const float k1 = Kt[d][kidx1];
            const float k2 = Kt[d][kidx2];
#pragma unroll
            for (int qi = 0; qi < 4; qi++) {
                const float qv = Qs[warp * 4 + qi][d];   // warp-broadcast
                lg[qi][0] += qv * k0;
                lg[qi][1] += qv * k1;
                lg[qi][2] += qv * k2;
            }
        }

#pragma unroll
        for (int qi = 0; qi < 4; qi++) {
            float l0 = v0 ? lg[qi][0] * 0.125f : -1e30f;
            float l1 = v1 ? lg[qi][1] * 0.125f : -1e30f;
            float l2 = v2 ? lg[qi][2] * 0.125f : -1e30f;
            float m = fmaxf(fmaxf(l0, l1), l2);
#pragma unroll
            for (int off = 16; off > 0; off >>= 1)
                m = fmaxf(m, __shfl_xor_sync(0xffffffffu, m, off));
            const float e0 = __expf(l0 - m);
            const float e1 = __expf(l1 - m);
            const float e2 = __expf(l2 - m);
            float s = e0 + e1 + e2;
#pragma unroll
            for (int off = 16; off > 0; off >>= 1)
                s += __shfl_xor_sync(0xffffffffu, s, off);
            const float inv = 1.f / s;
            acc[qi][0] += e0 * inv;
            acc[qi][1] += e1 * inv;
            acc[qi][2] += e2 * inv;
        }
        __syncthreads();
    }

    // scatter: out[q, rr*NNODES + k] = mean over heads
#pragma unroll
    for (int qi = 0; qi < 4; qi++) {
        const int q = qn[warp * 4 + qi];
        if (q < 0) continue;
        const size_t rowbase = (size_t)q * RN + (size_t)rr * NNODES;
        if (v0) out[rowbase + kn[kidx0]] = acc[qi][0] * 0.125f;
        if (v1) out[rowbase + kn[kidx1]] = acc[qi][1] * 0.125f;
        if (v2) out[rowbase + kn[kidx2]] = acc[qi][2] * 0.125f;
    }
}

// ---------------------------------------------------------------------------
extern "C" void kernel_launch(void* const* d_in, const int* in_sizes, int n_in,
                              void* d_out, int out_size)
{
    const float* nf = (const float*)d_in[0];   // [R, N, 256]
    const float* Wq = (const float*)d_in[1];   // [512, 256]
    const float* bq = (const float*)d_in[2];   // [512]
    const float* Wk = (const float*)d_in[3];   // [512, 256]
    const float* bk = (const float*)d_in[4];   // [512]
    // d_in[5] = num_nodes (int64) — static, baked into constants
    float* out = (float*)d_out;

    cudaMemsetAsync(out, 0, (size_t)out_size * sizeof(float));

    dim3 ggrid(8, (RN + 127) / 128);
    gemm_kernel<<<ggrid, 256>>>(nf, Wq, bq, Wk, bk);

    dim3 agrid(NWIN, RREL);
    attn_kernel<<<agrid, 256>>>(out);
}